// round 8
// baseline (speedup 1.0000x reference)
#include <cuda_runtime.h>

// ---------------------------------------------------------------------------
// ConfidenceAwareSSIM: B=16, C=3, H=W=512, fp32.
// loss = mean( clip(1 - SSIM(x,y), 0, 1) * conf ), 11x11 Gaussian, zero pad.
//
// R8 change vs R7 (76.3us):
//  * Latency-bound fix (issue=76.5%, occ=35%, no pipe saturated):
//    512-thread CTAs, 2 CTAs/SM. smem 2x75.8KB=151.5KB fits; 1024 thr x
//    64 regs = full regfile. Warps/SM 24 -> 32 (occ 50%), identical
//    per-pixel work (same 64x64 tile + halo). Phase 2 is now a single
//    8-row pass per thread (8 row-groups), fewer live regs + barriers.
// ---------------------------------------------------------------------------

#define BATCH 16
#define CH    3
#define HH    512
#define WW    512

#define TW    64
#define TH    64
#define HALO  5
#define SH    (TH + 2*HALO)       // 74
#define NTHR  512

#define SMEM_FLOATS (4*SH*TW)     // planes: S, D, A=conv(s^2), B=conv(d^2)
#define SMEM_BYTES  (SMEM_FLOATS * 4)   // 75,776 B

// Gaussian taps (symmetric, normalized) as literals.
__device__ __forceinline__ constexpr float gw(int k) {
    const int d = (k <= 5) ? k : (10 - k);
    return (d == 0) ? 0.00102838f
         : (d == 1) ? 0.00759876f
         : (d == 2) ? 0.03600078f
         : (d == 3) ? 0.10936070f
         : (d == 4) ? 0.21300554f
         :            0.26601173f;
}

__global__ void zero_out_kernel(float* p) { *p = 0.0f; }

__global__ void __launch_bounds__(NTHR, 2)
ssim_tile_kernel(const float* __restrict__ gx, const float* __restrict__ gy,
                 const float* __restrict__ gconf, float* __restrict__ gout)
{
    extern __shared__ float sh[];           // [4][SH][TW]

    const int tid = threadIdx.x;
    const int col = tid & 63;               // phase-2: one column per thread
    const int ry  = tid >> 6;               // phase-2: row group 0..7
    const int x0  = blockIdx.x * TW;
    const int y0  = blockIdx.y * TH;
    const int zc  = blockIdx.z;             // b*3 + c
    const int b   = zc / 3;
    const int c   = zc - 3 * b;

    const float C1c = 0.0001f;   // 0.01^2
    const float C2c = 0.0009f;   // 0.03^2

    const float* cbase = gconf + (size_t)b * (HH * WW) + (size_t)y0 * WW + (x0 + col);
    const float* xb = gx + (size_t)(b * CH + c) * (HH * WW);
    const float* yb = gy + (size_t)(b * CH + c) * (HH * WW);

    float tsum = 0.0f;           // running sum of loss*conf over my pixels

    // ---- Phase 1: horizontal conv of {s,d,s^2,d^2} from GLOBAL -> sh ----
    // Unit (r,g): smem row r, output cols 4g..4g+3. Taps span image cols
    // x0+4g-5 .. x0+4g+8, covered by 5 aligned float4s starting x0+4g-8.
    for (int u = tid; u < SH * 16; u += NTHR) {
        const int r = u >> 4;
        const int g = u & 15;
        const int grow = y0 + r - HALO;
        const bool rok = (unsigned)grow < (unsigned)HH;
        const float4* xrow = reinterpret_cast<const float4*>(xb + (size_t)grow * WW);
        const float4* yrow = reinterpret_cast<const float4*>(yb + (size_t)grow * WW);
        const int c0 = x0 + 4 * g - 8;     // first float4 col (aligned)

        float vs[20], vd[20];
#pragma unroll
        for (int q = 0; q < 5; ++q) {
            const int gc = c0 + 4 * q;
            float4 fx = make_float4(0.f, 0.f, 0.f, 0.f);
            float4 fy = make_float4(0.f, 0.f, 0.f, 0.f);
            if (rok && (unsigned)gc < (unsigned)WW) {
                fx = xrow[gc >> 2];
                fy = yrow[gc >> 2];
            }
            vs[4*q+0] = fx.x + fy.x;  vd[4*q+0] = fx.x - fy.x;
            vs[4*q+1] = fx.y + fy.y;  vd[4*q+1] = fx.y - fy.y;
            vs[4*q+2] = fx.z + fy.z;  vd[4*q+2] = fx.z - fy.z;
            vs[4*q+3] = fx.w + fy.w;  vd[4*q+3] = fx.w - fy.w;
        }

        // conv of s and d: direct FFMA chains
#pragma unroll
        for (int j = 0; j < 4; ++j) {
            float hs = vs[j+3] * gw(0);
            float hd = vd[j+3] * gw(0);
#pragma unroll
            for (int k = 1; k < 11; ++k) {
                hs = fmaf(vs[j+3+k], gw(k), hs);
                hd = fmaf(vd[j+3+k], gw(k), hd);
            }
            const int o = r * TW + 4 * g + j;
            sh[0*(SH*TW) + o] = hs;
            sh[1*(SH*TW) + o] = hd;
        }

        // squares (span indices 3..16 -> s2[0..13]) then their conv
        float s2[14], d2[14];
#pragma unroll
        for (int i = 0; i < 14; ++i) {
            s2[i] = vs[i+3] * vs[i+3];
            d2[i] = vd[i+3] * vd[i+3];
        }
#pragma unroll
        for (int j = 0; j < 4; ++j) {
            float hs2 = s2[j] * gw(0);
            float hd2 = d2[j] * gw(0);
#pragma unroll
            for (int k = 1; k < 11; ++k) {
                hs2 = fmaf(s2[j+k], gw(k), hs2);
                hd2 = fmaf(d2[j+k], gw(k), hd2);
            }
            const int o = r * TW + 4 * g + j;
            sh[2*(SH*TW) + o] = hs2;
            sh[3*(SH*TW) + o] = hd2;
        }
    }
    __syncthreads();

    // ---- Phase 2: single (8 rows x 1 col) pass, vertical conv + SSIM ----
    {
        const int rbase = 8 * ry;

        float resS[8];
        {
            const float* bp = sh + 0*(SH*TW) + col;
            float v[18];
#pragma unroll
            for (int r = 0; r < 18; ++r) v[r] = bp[(rbase + r) * TW];
#pragma unroll
            for (int j = 0; j < 8; ++j) {
                float a = v[j] * gw(0);
#pragma unroll
                for (int k = 1; k < 11; ++k) a = fmaf(v[j+k], gw(k), a);
                resS[j] = a;
            }
        }

        float t1[8], t3[8];
        {
            const float* bp = sh + 1*(SH*TW) + col;
            float v[18];
#pragma unroll
            for (int r = 0; r < 18; ++r) v[r] = bp[(rbase + r) * TW];
#pragma unroll
            for (int j = 0; j < 8; ++j) {
                float a = v[j] * gw(0);
#pragma unroll
                for (int k = 1; k < 11; ++k) a = fmaf(v[j+k], gw(k), a);
                const float P = resS[j] * resS[j];
                const float Q = a * a;
                t1[j] = 0.5f * (P - Q);        // 2*mu_x*mu_y
                t3[j] = 0.5f * (P + Q);        // mu_x^2 + mu_y^2
            }
        }

        float resA[8];
        {
            const float* bp = sh + 2*(SH*TW) + col;
            float v[18];
#pragma unroll
            for (int r = 0; r < 18; ++r) v[r] = bp[(rbase + r) * TW];
#pragma unroll
            for (int j = 0; j < 8; ++j) {
                float a = v[j] * gw(0);
#pragma unroll
                for (int k = 1; k < 11; ++k) a = fmaf(v[j+k], gw(k), a);
                resA[j] = a;
            }
        }

        {
            const float* bp = sh + 3*(SH*TW) + col;
            float v[18];
#pragma unroll
            for (int r = 0; r < 18; ++r) v[r] = bp[(rbase + r) * TW];
#pragma unroll
            for (int j = 0; j < 8; ++j) {
                float a = v[j] * gw(0);
#pragma unroll
                for (int k = 1; k < 11; ++k) a = fmaf(v[j+k], gw(k), a);
                const float t2 = 0.5f * (resA[j] - a) - t1[j];   // 2*sigma_xy
                const float t4 = 0.5f * (resA[j] + a) - t3[j];   // sx^2+sy^2
                const float num = (t1[j] + C1c) * (t2 + C2c);
                const float den = (t3[j] + C1c) * (t4 + C2c);
                float loss = 1.0f - __fdividef(num, den);
                loss = fminf(fmaxf(loss, 0.0f), 1.0f);
                tsum += loss * cbase[(size_t)(rbase + j) * WW];
            }
        }
    }

    // ---- block reduction + atomic ----
#pragma unroll
    for (int off = 16; off > 0; off >>= 1)
        tsum += __shfl_down_sync(0xffffffffu, tsum, off);

    __shared__ float wsum[16];
    if ((tid & 31) == 0) wsum[tid >> 5] = tsum;
    __syncthreads();
    if (tid == 0) {
        float s = 0.0f;
#pragma unroll
        for (int i = 0; i < 16; ++i) s += wsum[i];
        const float inv_n = 1.0f / (float)(BATCH * CH * HH * WW);
        atomicAdd(gout, s * inv_n);
    }
}

extern "C" void kernel_launch(void* const* d_in, const int* in_sizes, int n_in,
                              void* d_out, int out_size)
{
    const float* x    = (const float*)d_in[0];
    const float* y    = (const float*)d_in[1];
    const float* conf = (const float*)d_in[2];
    float* out = (float*)d_out;

    cudaFuncSetAttribute(ssim_tile_kernel,
                         cudaFuncAttributeMaxDynamicSharedMemorySize, SMEM_BYTES);

    zero_out_kernel<<<1, 1>>>(out);

    dim3 grid(WW / TW, HH / TH, BATCH * CH);   // 8 x 8 x 48 = 3072 blocks
    ssim_tile_kernel<<<grid, NTHR, SMEM_BYTES>>>(x, y, conf, out);
}

// round 9
// speedup vs baseline: 1.1117x; 1.1117x over previous
#include <cuda_runtime.h>

// ---------------------------------------------------------------------------
// ConfidenceAwareSSIM: B=16, C=3, H=W=512, fp32.
// loss = mean( clip(1 - SSIM(x,y), 0, 1) * conf ), 11x11 Gaussian, zero pad.
//
// R9 changes vs R7 (76.3us best; R8 occupancy experiment FAILED/reverted):
//  * zero_out kernel deleted (-3.3us launch overhead): block partial sums go
//    to a __device__ accumulator; the last CTA (ticket counter) writes gout
//    and resets the accumulator for the next graph replay.
//  * smem planes interleaved as float2 pairs (S,D) and (A,B): phase-1 STS
//    and phase-2 LDS instruction counts halve (64-bit ops), phase 2 merges
//    into two passes -> fewer issue slots on the non-fma side.
// ---------------------------------------------------------------------------

#define BATCH 16
#define CH    3
#define HH    512
#define WW    512

#define TW    64
#define TH    64
#define HALO  5
#define SH    (TH + 2*HALO)       // 74
#define NBLOCKS (8*8*48)

#define SMEM_FLOATS (4*SH*TW)     // two float2 planes: (S,D), (A,B)
#define SMEM_BYTES  (SMEM_FLOATS * 4)   // 75,776 B

// Gaussian taps (symmetric, normalized) as literals.
__device__ __forceinline__ constexpr float gw(int k) {
    const int d = (k <= 5) ? k : (10 - k);
    return (d == 0) ? 0.00102838f
         : (d == 1) ? 0.00759876f
         : (d == 2) ? 0.03600078f
         : (d == 3) ? 0.10936070f
         : (d == 4) ? 0.21300554f
         :            0.26601173f;
}

__device__ float    g_accum  = 0.0f;
__device__ unsigned g_ticket = 0u;

__global__ void __launch_bounds__(256, 3)
ssim_tile_kernel(const float* __restrict__ gx, const float* __restrict__ gy,
                 const float* __restrict__ gconf, float* __restrict__ gout)
{
    extern __shared__ float smem_raw[];
    float2* shSD = reinterpret_cast<float2*>(smem_raw);   // [SH][TW] (S,D)
    float2* shAB = shSD + SH * TW;                        // [SH][TW] (A,B)

    const int tid = threadIdx.x;
    const int col = tid & 63;               // phase-2: one column per thread
    const int ry  = tid >> 6;               // phase-2: row group 0..3
    const int x0  = blockIdx.x * TW;
    const int y0  = blockIdx.y * TH;
    const int zc  = blockIdx.z;             // b*3 + c
    const int b   = zc / 3;
    const int c   = zc - 3 * b;

    const float C1c = 0.0001f;   // 0.01^2
    const float C2c = 0.0009f;   // 0.03^2

    const float* cbase = gconf + (size_t)b * (HH * WW) + (size_t)y0 * WW + (x0 + col);
    const float* xb = gx + (size_t)(b * CH + c) * (HH * WW);
    const float* yb = gy + (size_t)(b * CH + c) * (HH * WW);

    float tsum = 0.0f;           // running sum of loss*conf over my pixels

    // ---- Phase 1: horizontal conv of {s,d,s^2,d^2} from GLOBAL -> smem ----
    // Unit (r,g): smem row r, output cols 4g..4g+3. Taps span image cols
    // x0+4g-5 .. x0+4g+8, covered by 5 aligned float4s starting x0+4g-8.
    for (int u = tid; u < SH * 16; u += 256) {
        const int r = u >> 4;
        const int g = u & 15;
        const int grow = y0 + r - HALO;
        const bool rok = (unsigned)grow < (unsigned)HH;
        const float4* xrow = reinterpret_cast<const float4*>(xb + (size_t)grow * WW);
        const float4* yrow = reinterpret_cast<const float4*>(yb + (size_t)grow * WW);
        const int c0 = x0 + 4 * g - 8;     // first float4 col (aligned)

        float vs[20], vd[20];
#pragma unroll
        for (int q = 0; q < 5; ++q) {
            const int gc = c0 + 4 * q;
            float4 fx = make_float4(0.f, 0.f, 0.f, 0.f);
            float4 fy = make_float4(0.f, 0.f, 0.f, 0.f);
            if (rok && (unsigned)gc < (unsigned)WW) {
                fx = xrow[gc >> 2];
                fy = yrow[gc >> 2];
            }
            vs[4*q+0] = fx.x + fy.x;  vd[4*q+0] = fx.x - fy.x;
            vs[4*q+1] = fx.y + fy.y;  vd[4*q+1] = fx.y - fy.y;
            vs[4*q+2] = fx.z + fy.z;  vd[4*q+2] = fx.z - fy.z;
            vs[4*q+3] = fx.w + fy.w;  vd[4*q+3] = fx.w - fy.w;
        }

        // conv of s and d -> interleaved (S,D) store
#pragma unroll
        for (int j = 0; j < 4; ++j) {
            float hs = vs[j+3] * gw(0);
            float hd = vd[j+3] * gw(0);
#pragma unroll
            for (int k = 1; k < 11; ++k) {
                hs = fmaf(vs[j+3+k], gw(k), hs);
                hd = fmaf(vd[j+3+k], gw(k), hd);
            }
            shSD[r * TW + 4 * g + j] = make_float2(hs, hd);
        }

        // squares (span indices 3..16 -> s2[0..13]) then their conv
        float s2[14], d2[14];
#pragma unroll
        for (int i = 0; i < 14; ++i) {
            s2[i] = vs[i+3] * vs[i+3];
            d2[i] = vd[i+3] * vd[i+3];
        }
#pragma unroll
        for (int j = 0; j < 4; ++j) {
            float hs2 = s2[j] * gw(0);
            float hd2 = d2[j] * gw(0);
#pragma unroll
            for (int k = 1; k < 11; ++k) {
                hs2 = fmaf(s2[j+k], gw(k), hs2);
                hd2 = fmaf(d2[j+k], gw(k), hd2);
            }
            shAB[r * TW + 4 * g + j] = make_float2(hs2, hd2);
        }
    }
    __syncthreads();

    // ---- Phase 2: two passes of (8 rows x 1 col), vertical conv + SSIM ----
#pragma unroll
    for (int pass = 0; pass < 2; ++pass) {
        const int rbase = 8 * ry + 32 * pass;

        float t1[8], t3[8];
        {
            const float2* bp = shSD + col;
            float2 v[18];
#pragma unroll
            for (int r = 0; r < 18; ++r) v[r] = bp[(rbase + r) * TW];
#pragma unroll
            for (int j = 0; j < 8; ++j) {
                float aS = v[j].x * gw(0);
                float aD = v[j].y * gw(0);
#pragma unroll
                for (int k = 1; k < 11; ++k) {
                    aS = fmaf(v[j+k].x, gw(k), aS);
                    aD = fmaf(v[j+k].y, gw(k), aD);
                }
                const float P = aS * aS;
                const float Q = aD * aD;
                t1[j] = 0.5f * (P - Q);        // 2*mu_x*mu_y
                t3[j] = 0.5f * (P + Q);        // mu_x^2 + mu_y^2
            }
        }

        {
            const float2* bp = shAB + col;
            float2 v[18];
#pragma unroll
            for (int r = 0; r < 18; ++r) v[r] = bp[(rbase + r) * TW];
#pragma unroll
            for (int j = 0; j < 8; ++j) {
                float aA = v[j].x * gw(0);
                float aB = v[j].y * gw(0);
#pragma unroll
                for (int k = 1; k < 11; ++k) {
                    aA = fmaf(v[j+k].x, gw(k), aA);
                    aB = fmaf(v[j+k].y, gw(k), aB);
                }
                const float t2 = 0.5f * (aA - aB) - t1[j];   // 2*sigma_xy
                const float t4 = 0.5f * (aA + aB) - t3[j];   // sx^2+sy^2
                const float num = (t1[j] + C1c) * (t2 + C2c);
                const float den = (t3[j] + C1c) * (t4 + C2c);
                float loss = 1.0f - __fdividef(num, den);
                loss = fminf(fmaxf(loss, 0.0f), 1.0f);
                tsum += loss * cbase[(size_t)(rbase + j) * WW];
            }
        }
    }

    // ---- block reduction + device-global accumulation + finalize ----
#pragma unroll
    for (int off = 16; off > 0; off >>= 1)
        tsum += __shfl_down_sync(0xffffffffu, tsum, off);

    __shared__ float wsum[8];
    if ((tid & 31) == 0) wsum[tid >> 5] = tsum;
    __syncthreads();
    if (tid == 0) {
        float s = 0.0f;
#pragma unroll
        for (int i = 0; i < 8; ++i) s += wsum[i];
        atomicAdd(&g_accum, s);
        __threadfence();
        const unsigned t = atomicAdd(&g_ticket, 1u);
        if (t == NBLOCKS - 1) {
            const float total = *((volatile float*)&g_accum);
            const float inv_n = 1.0f / (float)(BATCH * CH * HH * WW);
            *gout = total * inv_n;
            g_accum  = 0.0f;      // reset for next graph replay
            g_ticket = 0u;
        }
    }
}

extern "C" void kernel_launch(void* const* d_in, const int* in_sizes, int n_in,
                              void* d_out, int out_size)
{
    const float* x    = (const float*)d_in[0];
    const float* y    = (const float*)d_in[1];
    const float* conf = (const float*)d_in[2];
    float* out = (float*)d_out;

    cudaFuncSetAttribute(ssim_tile_kernel,
                         cudaFuncAttributeMaxDynamicSharedMemorySize, SMEM_BYTES);

    dim3 grid(WW / TW, HH / TH, BATCH * CH);   // 8 x 8 x 48 = 3072 blocks
    ssim_tile_kernel<<<grid, 256, SMEM_BYTES>>>(x, y, conf, out);
}